// round 10
// baseline (speedup 1.0000x reference)
#include <cuda_runtime.h>
#include <cuda_fp16.h>
#include <cstdint>

#define NN 16384
#define KK 1024
#define DD 512
#define ITERS 20
#define HSCALE 16.0f
#define INV_HSCALE (1.0f/16.0f)
#define MU_F (1.0f/16384.0f)
#define NU_F (1.0f/1024.0f)
#define USCALE 1024.0f
#define S_DIV (INV_HSCALE / USCALE)     // s_stored * S_DIV = true (K^T u) sum
#define LOOP_GRID 256

// ---------------- scratch (static device globals; no runtime allocation) ----------------
__device__ float  g_C[(size_t)NN * KK];        // raw cost matrix (64 MB)
__device__ __half g_Kh[(size_t)NN * KK];       // K_eps * 16 in fp16 (32 MB)
__device__ __half g_xh[(size_t)NN * DD];       // fp16 copy of x
__device__ __half g_ph[(size_t)KK * DD];       // fp16 copy of p
__device__ float  g_u[NN];
__device__ float  g_s[ITERS + 1][KK];          // time-indexed column sums (x16*1024 scaled)
__device__ float  g_dx[NN];
__device__ float  g_dp[KK];
__device__ int    g_cmax_bits;
__device__ unsigned g_bar[ITERS];              // per-iteration grid-barrier counters

__device__ __forceinline__ float v_of_s(float s) {
    return __fdividef(NU_F, s * S_DIV + 1e-8f);
}

// ---- packed f32x2 helpers (Blackwell FFMA2) ----
__device__ __forceinline__ unsigned long long pack2(float lo, float hi) {
    unsigned long long r;
    asm("mov.b64 %0, {%1, %2};" : "=l"(r) : "f"(lo), "f"(hi));
    return r;
}
__device__ __forceinline__ void fma2(unsigned long long& d,
                                     unsigned long long a,
                                     unsigned long long b) {
    asm("fma.rn.f32x2 %0, %1, %2, %0;" : "+l"(d) : "l"(a), "l"(b));
}
__device__ __forceinline__ float2 unpack2(unsigned long long v) {
    float lo, hi;
    asm("mov.b64 {%0, %1}, %2;" : "=f"(lo), "=f"(hi) : "l"(v));
    return make_float2(lo, hi);
}
__device__ __forceinline__ unsigned long long h2tof2(unsigned h) {
    unsigned long long r;
    asm("{.reg .b16 l, h;\n\t"
        ".reg .f32 fl, fh;\n\t"
        "mov.b32 {l, h}, %1;\n\t"
        "cvt.f32.f16 fl, l;\n\t"
        "cvt.f32.f16 fh, h;\n\t"
        "mov.b64 %0, {fl, fh};}" : "=l"(r) : "r"(h));
    return r;
}
__device__ __forceinline__ __half2 u32h2(unsigned v) {
    return *reinterpret_cast<__half2*>(&v);
}

__device__ __forceinline__ uint32_t s2u(const void* p) {
    uint32_t r;
    asm("{ .reg .u64 t; cvta.to.shared.u64 t, %1; cvt.u32.u64 %0, t; }" : "=r"(r) : "l"(p));
    return r;
}
__device__ __forceinline__ void cp16u(uint32_t dst, const void* src) {
    asm volatile("cp.async.cg.shared.global [%0], [%1], 16;" :: "r"(dst), "l"(src));
}
__device__ __forceinline__ void ldsm4(unsigned* r, uint32_t a) {
    asm volatile("ldmatrix.sync.aligned.m8n8.x4.shared.b16 {%0,%1,%2,%3}, [%4];"
        : "=r"(r[0]), "=r"(r[1]), "=r"(r[2]), "=r"(r[3]) : "r"(a));
}
__device__ __forceinline__ void mma_f16(float* d, const unsigned* a,
                                        unsigned b0, unsigned b1) {
    asm volatile(
        "mma.sync.aligned.m16n8k16.row.col.f32.f16.f16.f32 "
        "{%0,%1,%2,%3}, {%4,%5,%6,%7}, {%8,%9}, {%0,%1,%2,%3};"
        : "+f"(d[0]), "+f"(d[1]), "+f"(d[2]), "+f"(d[3])
        : "r"(a[0]), "r"(a[1]), "r"(a[2]), "r"(a[3]), "r"(b0), "r"(b1));
}

// ---------------- init: s[0] -> v==1, s[1..20]=0, barriers=0, cmax=0, loss slot=0 ----------------
__global__ void init_kernel(float* __restrict__ out) {
    const float S0 = (NU_F - 1e-8f) / S_DIV;   // makes v_of_s(S0) == 1
    int t = blockIdx.x * 256 + threadIdx.x;
    if (t < (ITERS + 1) * KK)
        (&g_s[0][0])[t] = (t < KK) ? S0 : 0.0f;
    if (t < ITERS) g_bar[t] = 0u;
    if (t == 0) { g_cmax_bits = 0; out[(size_t)NN * KK] = 0.0f; }
}

// ---------------- convert f32 -> fp16 + row squared norm ----------------
__global__ void split_kernel(const float* __restrict__ src, int which) {
    int row = blockIdx.x;
    int t = threadIdx.x;  // 128 threads, 4 floats each
    float4 v = reinterpret_cast<const float4*>(src + (size_t)row * DD)[t];

    __half2 h0 = __floats2half2_rn(v.x, v.y);
    __half2 h1 = __floats2half2_rn(v.z, v.w);
    __half* dh = which ? g_ph : g_xh;
    uint2 pk;
    pk.x = *reinterpret_cast<unsigned*>(&h0);
    pk.y = *reinterpret_cast<unsigned*>(&h1);
    *reinterpret_cast<uint2*>(dh + (size_t)row * DD + t * 4) = pk;

    float nrm = v.x * v.x + v.y * v.y + v.z * v.z + v.w * v.w;
#pragma unroll
    for (int o = 16; o; o >>= 1) nrm += __shfl_xor_sync(0xffffffffu, nrm, o);
    __shared__ float w[4];
    int lane = t & 31, wid = t >> 5;
    if (!lane) w[wid] = nrm;
    __syncthreads();
    if (t == 0) {
        float s = w[0] + w[1] + w[2] + w[3];
        if (which == 0) g_dx[row] = s; else g_dp[row] = s;
    }
}

// ---------------- HMMA GEMM (single-pass fp16) + cost epilogue ----------------
#define BK 64
#define NCHUNK (DD / BK)          // 8
#define ROWB 144                  // bytes per 64-element fp16 row (128 + 16 pad)
#define PARTB (128 * ROWB)        // 18432
#define STAGEB (2 * PARTB)        // 36864: [A, B]
#define GEMM_SMEM (2 * STAGEB)    // 73728

__device__ __forceinline__ void load_chunk(uint32_t st, int bm, int bn, int k0, int tid) {
#pragma unroll
    for (int part = 0; part < 2; part++) {
        const __half* src = part ? g_ph : g_xh;
        const int rbase = part ? bn : bm;
        uint32_t dst = st + part * PARTB;
#pragma unroll
        for (int i = 0; i < 4; i++) {
            int g = tid + i * 256;
            int row = g >> 3, c = g & 7;
            cp16u(dst + row * ROWB + c * 16,
                  src + (size_t)(rbase + row) * DD + k0 + c * 8);
        }
    }
}

__global__ __launch_bounds__(256, 2)
void gemm_mma_kernel() {
    extern __shared__ __align__(16) char smem[];
    __shared__ float dpc[128];
    const uint32_t sb = s2u(smem);
    const int tid = threadIdx.x;
    const int wid = tid >> 5, lane = tid & 31;
    const int g = lane >> 2;
    const int t2 = (lane & 3) * 2;
    const int warpM = wid & 3, warpN = wid >> 2;
    const int bn = blockIdx.x * 128;
    const int bm = blockIdx.y * 128;

    if (tid < 128) dpc[tid] = g_dp[bn + tid];

    const uint32_t aoff = (uint32_t)((warpM * 32 + (lane & 15)) * ROWB + (lane >> 4) * 16);
    const uint32_t boff = (uint32_t)((warpN * 64 + (lane & 15)) * ROWB + (lane >> 4) * 16);

    float d[2][8][4];
#pragma unroll
    for (int mi = 0; mi < 2; mi++)
#pragma unroll
        for (int ni = 0; ni < 8; ni++)
#pragma unroll
            for (int q = 0; q < 4; q++) d[mi][ni][q] = 0.0f;

    load_chunk(sb, bm, bn, 0, tid);
    asm volatile("cp.async.commit_group;");

    for (int s = 0; s < NCHUNK; s++) {
        if (s + 1 < NCHUNK) {
            load_chunk(sb + ((s + 1) & 1) * STAGEB, bm, bn, (s + 1) * BK, tid);
            asm volatile("cp.async.commit_group;");
            asm volatile("cp.async.wait_group 1;");
        } else {
            asm volatile("cp.async.wait_group 0;");
        }
        __syncthreads();

        const uint32_t A = sb + (s & 1) * STAGEB;
        const uint32_t B = A + PARTB;

#pragma unroll
        for (int ks = 0; ks < 4; ks++) {
            unsigned a[2][4], b[4][4];
            ldsm4(a[0], A + aoff + ks * 32);
            ldsm4(a[1], A + aoff + 16 * ROWB + ks * 32);
#pragma unroll
            for (int q = 0; q < 4; q++)
                ldsm4(b[q], B + boff + q * 16 * ROWB + ks * 32);
#pragma unroll
            for (int q = 0; q < 4; q++)
#pragma unroll
                for (int mi = 0; mi < 2; mi++) {
                    mma_f16(d[mi][2 * q],     a[mi], b[q][0], b[q][2]);
                    mma_f16(d[mi][2 * q + 1], a[mi], b[q][1], b[q][3]);
                }
        }
        __syncthreads();
    }

    float tmax = 0.0f;
#pragma unroll
    for (int mi = 0; mi < 2; mi++) {
#pragma unroll
        for (int h = 0; h < 2; h++) {
            int row = bm + warpM * 32 + mi * 16 + h * 8 + g;
            float dxr = g_dx[row];
            float* cp = g_C + (size_t)row * KK + bn + warpN * 64;
#pragma unroll
            for (int ni = 0; ni < 8; ni++) {
                int c0 = ni * 8 + t2;
                float o0 = dxr + dpc[warpN * 64 + c0]     - 2.0f * d[mi][ni][h * 2];
                float o1 = dxr + dpc[warpN * 64 + c0 + 1] - 2.0f * d[mi][ni][h * 2 + 1];
                tmax = fmaxf(tmax, fmaxf(o0, o1));
                *reinterpret_cast<float2*>(cp + c0) = make_float2(o0, o1);
            }
        }
    }
#pragma unroll
    for (int o = 16; o; o >>= 1)
        tmax = fmaxf(tmax, __shfl_xor_sync(0xffffffffu, tmax, o));
    if (!lane) atomicMax(&g_cmax_bits, __float_as_int(tmax));
}

// ---------------- K_eps (fp16, x16 scaled): Kh = 16 * exp(-C / ((max+1e-8)*0.1)) ----------------
__global__ void expk_kernel() {
    float negK = -10.0f / (__int_as_float(g_cmax_bits) + 1e-8f);
    size_t nvec = (size_t)NN * KK / 4;
    size_t stride = (size_t)gridDim.x * blockDim.x;
    for (size_t t = (size_t)blockIdx.x * blockDim.x + threadIdx.x; t < nvec; t += stride) {
        float4 c = *reinterpret_cast<const float4*>(g_C + t * 4);
        __half2 h0 = __floats2half2_rn(__expf(c.x * negK) * HSCALE,
                                       __expf(c.y * negK) * HSCALE);
        __half2 h1 = __floats2half2_rn(__expf(c.z * negK) * HSCALE,
                                       __expf(c.w * negK) * HSCALE);
        uint2 pk;
        pk.x = *reinterpret_cast<unsigned*>(&h0);
        pk.y = *reinterpret_cast<unsigned*>(&h1);
        *reinterpret_cast<uint2*>(g_Kh + t * 4) = pk;
    }
}

// ---------------- persistent Sinkhorn loop: all 20 iterations, one launch ----------------
// 256 blocks (single wave at 2 blocks/SM), software grid barrier between iterations.
// Per iteration: v(s[it]) inline, u-step (f32x2 dot), colacc (HFMA2) -> atomics to s[it+1].
#define RPW 8
#define ROWS_PER_BLOCK (8 * RPW)   // 64 rows * 256 blocks = 16384
__global__ __launch_bounds__(256, 2)
void sinkhorn_loop_kernel() {
    const int tid = threadIdx.x;
    const int lane = tid & 31;
    const int wid  = tid >> 5;
    const int rowbase = blockIdx.x * ROWS_PER_BLOCK + wid * RPW;
    __shared__ float sm[8][KK];

    for (int it = 0; it < ITERS; it++) {
        const float* __restrict__ sprev = g_s[it];
        float* __restrict__ snext = g_s[it + 1];

        // v packed as f32x2 pairs matching half2 load layout
        unsigned long long vrp[16];
#pragma unroll
        for (int q = 0; q < 4; q++) {
            int e = (lane + 32 * q) * 8;
            float4 a = *reinterpret_cast<const float4*>(sprev + e);
            float4 b = *reinterpret_cast<const float4*>(sprev + e + 4);
            vrp[4 * q + 0] = pack2(v_of_s(a.x), v_of_s(a.y));
            vrp[4 * q + 1] = pack2(v_of_s(a.z), v_of_s(a.w));
            vrp[4 * q + 2] = pack2(v_of_s(b.x), v_of_s(b.y));
            vrp[4 * q + 3] = pack2(v_of_s(b.z), v_of_s(b.w));
        }
        __half2 colh[16];
#pragma unroll
        for (int j = 0; j < 16; j++) colh[j] = __half2half2(__float2half(0.0f));

#pragma unroll
        for (int pr = 0; pr < RPW / 2; pr++) {
            const int r0 = rowbase + 2 * pr;
            const __half* p0 = g_Kh + (size_t)r0 * KK;
            const __half* p1 = p0 + KK;
            uint4 raw0[4], raw1[4];
#pragma unroll
            for (int q = 0; q < 4; q++) {
                int e = (lane + 32 * q) * 8;
                raw0[q] = *reinterpret_cast<const uint4*>(p0 + e);
                raw1[q] = *reinterpret_cast<const uint4*>(p1 + e);
            }
            unsigned long long a0 = 0, b0 = 0, a1 = 0, b1 = 0;
#pragma unroll
            for (int q = 0; q < 4; q++) {
                fma2(a0, h2tof2(raw0[q].x), vrp[4 * q + 0]);
                fma2(b0, h2tof2(raw0[q].y), vrp[4 * q + 1]);
                fma2(a0, h2tof2(raw0[q].z), vrp[4 * q + 2]);
                fma2(b0, h2tof2(raw0[q].w), vrp[4 * q + 3]);
                fma2(a1, h2tof2(raw1[q].x), vrp[4 * q + 0]);
                fma2(b1, h2tof2(raw1[q].y), vrp[4 * q + 1]);
                fma2(a1, h2tof2(raw1[q].z), vrp[4 * q + 2]);
                fma2(b1, h2tof2(raw1[q].w), vrp[4 * q + 3]);
            }
            float2 f0a = unpack2(a0), f0b = unpack2(b0);
            float2 f1a = unpack2(a1), f1b = unpack2(b1);
            float dot0 = (f0a.x + f0a.y) + (f0b.x + f0b.y);
            float dot1 = (f1a.x + f1a.y) + (f1b.x + f1b.y);
#pragma unroll
            for (int o = 16; o; o >>= 1) {
                dot0 += __shfl_xor_sync(0xffffffffu, dot0, o);
                dot1 += __shfl_xor_sync(0xffffffffu, dot1, o);
            }
            float u0 = __fdividef(MU_F, dot0 * INV_HSCALE + 1e-8f);
            float u1 = __fdividef(MU_F, dot1 * INV_HSCALE + 1e-8f);
            if (!lane) {
                g_u[r0] = u0;
                g_u[r0 + 1] = u1;
            }
            __half2 u0h = __float2half2_rn(u0 * USCALE);
            __half2 u1h = __float2half2_rn(u1 * USCALE);
#pragma unroll
            for (int q = 0; q < 4; q++) {
                colh[4*q+0] = __hfma2(u32h2(raw0[q].x), u0h, colh[4*q+0]);
                colh[4*q+1] = __hfma2(u32h2(raw0[q].y), u0h, colh[4*q+1]);
                colh[4*q+2] = __hfma2(u32h2(raw0[q].z), u0h, colh[4*q+2]);
                colh[4*q+3] = __hfma2(u32h2(raw0[q].w), u0h, colh[4*q+3]);
                colh[4*q+0] = __hfma2(u32h2(raw1[q].x), u1h, colh[4*q+0]);
                colh[4*q+1] = __hfma2(u32h2(raw1[q].y), u1h, colh[4*q+1]);
                colh[4*q+2] = __hfma2(u32h2(raw1[q].z), u1h, colh[4*q+2]);
                colh[4*q+3] = __hfma2(u32h2(raw1[q].w), u1h, colh[4*q+3]);
            }
        }

        // block-level reduction of column partials, then one atomic per col per block
        __syncthreads();   // protect smem reuse across iterations
#pragma unroll
        for (int q = 0; q < 4; q++) {
            int e = (lane + 32 * q) * 8;
            float2 c0 = __half22float2(colh[4*q+0]);
            float2 c1 = __half22float2(colh[4*q+1]);
            float2 c2 = __half22float2(colh[4*q+2]);
            float2 c3 = __half22float2(colh[4*q+3]);
            *reinterpret_cast<float4*>(&sm[wid][e])     = make_float4(c0.x, c0.y, c1.x, c1.y);
            *reinterpret_cast<float4*>(&sm[wid][e + 4]) = make_float4(c2.x, c2.y, c3.x, c3.y);
        }
        __syncthreads();
#pragma unroll
        for (int c = 0; c < 4; c++) {
            int col = tid + c * 256;
            float s = sm[0][col];
#pragma unroll
            for (int w = 1; w < 8; w++) s += sm[w][col];
            atomicAdd(&snext[col], s);
        }

        // grid barrier (skip after last iteration; kernel end syncs)
        if (it + 1 < ITERS) {
            __threadfence();
            __syncthreads();
            if (tid == 0) {
                atomicAdd(&g_bar[it], 1u);
                while (*((volatile unsigned*)&g_bar[it]) < LOOP_GRID) { }
            }
            __syncthreads();
        }
    }
}

// ---------------- final: T = u * exp(-Cn/eps) * v(s[20]), loss = sum(T * Cn) ----------------
__global__ __launch_bounds__(256)
void final_kernel(float* __restrict__ out) {
    float invM = 1.0f / (__int_as_float(g_cmax_bits) + 1e-8f);
    const float* __restrict__ slast = g_s[ITERS];
    size_t nvec = (size_t)NN * KK / 4;
    size_t stride = (size_t)gridDim.x * blockDim.x;
    float lsum = 0.f;
    for (size_t t = (size_t)blockIdx.x * blockDim.x + threadIdx.x; t < nvec; t += stride) {
        size_t base = t * 4;
        int i = (int)(base >> 10);
        int j = (int)(base & 1023);
        float4 c = *reinterpret_cast<const float4*>(g_C + base);
        float4 sj = *reinterpret_cast<const float4*>(slast + j);
        float ui = g_u[i];
        float cn0 = c.x * invM, cn1 = c.y * invM, cn2 = c.z * invM, cn3 = c.w * invM;
        float t0 = ui * __expf(-cn0 * 10.0f) * v_of_s(sj.x);
        float t1 = ui * __expf(-cn1 * 10.0f) * v_of_s(sj.y);
        float t2 = ui * __expf(-cn2 * 10.0f) * v_of_s(sj.z);
        float t3 = ui * __expf(-cn3 * 10.0f) * v_of_s(sj.w);
        *reinterpret_cast<float4*>(out + base) = make_float4(t0, t1, t2, t3);
        lsum += t0 * cn0 + t1 * cn1 + t2 * cn2 + t3 * cn3;
    }
#pragma unroll
    for (int o = 16; o; o >>= 1) lsum += __shfl_xor_sync(0xffffffffu, lsum, o);
    __shared__ float ws[8];
    int lane = threadIdx.x & 31, wid = threadIdx.x >> 5;
    if (!lane) ws[wid] = lsum;
    __syncthreads();
    if (threadIdx.x == 0) {
        float s = 0.f;
#pragma unroll
        for (int i = 0; i < 8; i++) s += ws[i];
        atomicAdd(out + (size_t)NN * KK, s);
    }
}

// ---------------- launch ----------------
extern "C" void kernel_launch(void* const* d_in, const int* in_sizes, int n_in,
                              void* d_out, int out_size) {
    const float* x = (const float*)d_in[0];   // [16384, 512]
    const float* p = (const float*)d_in[1];   // [1024, 512]
    float* out = (float*)d_out;               // T_star [16384,1024] then loss scalar

    cudaFuncSetAttribute(gemm_mma_kernel,
                         cudaFuncAttributeMaxDynamicSharedMemorySize, GEMM_SMEM);

    init_kernel<<<(((ITERS + 1) * KK) + 255) / 256, 256>>>(out);
    split_kernel<<<NN, 128>>>(x, 0);
    split_kernel<<<KK, 128>>>(p, 1);
    gemm_mma_kernel<<<dim3(KK / 128, NN / 128), 256, GEMM_SMEM>>>();
    expk_kernel<<<4096, 256>>>();
    sinkhorn_loop_kernel<<<LOOP_GRID, 256>>>();
    final_kernel<<<2048, 256>>>(out);
}

// round 11
// speedup vs baseline: 1.1155x; 1.1155x over previous
#include <cuda_runtime.h>
#include <cuda_fp16.h>
#include <cstdint>

#define NN 16384
#define KK 1024
#define DD 512
#define ITERS 20
#define HSCALE 16.0f
#define INV_HSCALE (1.0f/16.0f)
#define MU_F (1.0f/16384.0f)
#define NU_F (1.0f/1024.0f)
#define USCALE 1024.0f
#define S_DIV (INV_HSCALE / USCALE)     // s_stored * S_DIV = true (K^T u) sum
#define LN16 2.7725887222397812f

// ---------------- scratch (static device globals; no runtime allocation) ----------------
__device__ float  g_C[(size_t)NN * KK];        // raw cost matrix (64 MB)
__device__ __half g_Kh[(size_t)NN * KK];       // K_eps * 16 in fp16 (32 MB)
__device__ __half g_xh[(size_t)NN * DD];       // fp16 copy of x
__device__ __half g_ph[(size_t)KK * DD];       // fp16 copy of p
__device__ float  g_u[NN];
__device__ float  g_s[ITERS + 1][KK];          // time-indexed column sums (x16*1024 scaled)
__device__ float  g_dx[NN];
__device__ float  g_dp[KK];
__device__ int    g_cmax_bits;

__device__ __forceinline__ float v_of_s(float s) {
    return __fdividef(NU_F, s * S_DIV + 1e-8f);
}

// ---- packed f32x2 helpers (Blackwell FFMA2) ----
__device__ __forceinline__ unsigned long long pack2(float lo, float hi) {
    unsigned long long r;
    asm("mov.b64 %0, {%1, %2};" : "=l"(r) : "f"(lo), "f"(hi));
    return r;
}
__device__ __forceinline__ void fma2(unsigned long long& d,
                                     unsigned long long a,
                                     unsigned long long b) {
    asm("fma.rn.f32x2 %0, %1, %2, %0;" : "+l"(d) : "l"(a), "l"(b));
}
__device__ __forceinline__ float2 unpack2(unsigned long long v) {
    float lo, hi;
    asm("mov.b64 {%0, %1}, %2;" : "=f"(lo), "=f"(hi) : "l"(v));
    return make_float2(lo, hi);
}
__device__ __forceinline__ unsigned long long h2tof2(unsigned h) {
    unsigned long long r;
    asm("{.reg .b16 l, h;\n\t"
        ".reg .f32 fl, fh;\n\t"
        "mov.b32 {l, h}, %1;\n\t"
        "cvt.f32.f16 fl, l;\n\t"
        "cvt.f32.f16 fh, h;\n\t"
        "mov.b64 %0, {fl, fh};}" : "=l"(r) : "r"(h));
    return r;
}
__device__ __forceinline__ __half2 u32h2(unsigned v) {
    return *reinterpret_cast<__half2*>(&v);
}
__device__ __forceinline__ void prefetchL1(const void* p) {
    asm volatile("prefetch.global.L1 [%0];" :: "l"(p));
}

__device__ __forceinline__ uint32_t s2u(const void* p) {
    uint32_t r;
    asm("{ .reg .u64 t; cvta.to.shared.u64 t, %1; cvt.u32.u64 %0, t; }" : "=r"(r) : "l"(p));
    return r;
}
__device__ __forceinline__ void cp16u(uint32_t dst, const void* src) {
    asm volatile("cp.async.cg.shared.global [%0], [%1], 16;" :: "r"(dst), "l"(src));
}
__device__ __forceinline__ void ldsm4(unsigned* r, uint32_t a) {
    asm volatile("ldmatrix.sync.aligned.m8n8.x4.shared.b16 {%0,%1,%2,%3}, [%4];"
        : "=r"(r[0]), "=r"(r[1]), "=r"(r[2]), "=r"(r[3]) : "r"(a));
}
__device__ __forceinline__ void mma_f16(float* d, const unsigned* a,
                                        unsigned b0, unsigned b1) {
    asm volatile(
        "mma.sync.aligned.m16n8k16.row.col.f32.f16.f16.f32 "
        "{%0,%1,%2,%3}, {%4,%5,%6,%7}, {%8,%9}, {%0,%1,%2,%3};"
        : "+f"(d[0]), "+f"(d[1]), "+f"(d[2]), "+f"(d[3])
        : "r"(a[0]), "r"(a[1]), "r"(a[2]), "r"(a[3]), "r"(b0), "r"(b1));
}

// ---------------- init: s[0] -> v==1, s[1..20]=0, cmax=0, loss slot=0 ----------------
__global__ void init_kernel(float* __restrict__ out) {
    const float S0 = (NU_F - 1e-8f) / S_DIV;   // makes v_of_s(S0) == 1
    int t = blockIdx.x * 256 + threadIdx.x;
    if (t < (ITERS + 1) * KK)
        (&g_s[0][0])[t] = (t < KK) ? S0 : 0.0f;
    if (t == 0) { g_cmax_bits = 0; out[(size_t)NN * KK] = 0.0f; }
}

// ---------------- convert f32 -> fp16 + row squared norm ----------------
__global__ void split_kernel(const float* __restrict__ src, int which) {
    int row = blockIdx.x;
    int t = threadIdx.x;  // 128 threads, 4 floats each
    float4 v = reinterpret_cast<const float4*>(src + (size_t)row * DD)[t];

    __half2 h0 = __floats2half2_rn(v.x, v.y);
    __half2 h1 = __floats2half2_rn(v.z, v.w);
    __half* dh = which ? g_ph : g_xh;
    uint2 pk;
    pk.x = *reinterpret_cast<unsigned*>(&h0);
    pk.y = *reinterpret_cast<unsigned*>(&h1);
    *reinterpret_cast<uint2*>(dh + (size_t)row * DD + t * 4) = pk;

    float nrm = v.x * v.x + v.y * v.y + v.z * v.z + v.w * v.w;
#pragma unroll
    for (int o = 16; o; o >>= 1) nrm += __shfl_xor_sync(0xffffffffu, nrm, o);
    __shared__ float w[4];
    int lane = t & 31, wid = t >> 5;
    if (!lane) w[wid] = nrm;
    __syncthreads();
    if (t == 0) {
        float s = w[0] + w[1] + w[2] + w[3];
        if (which == 0) g_dx[row] = s; else g_dp[row] = s;
    }
}

// ---------------- HMMA GEMM (single-pass fp16) + cost epilogue ----------------
#define BK 64
#define NCHUNK (DD / BK)          // 8
#define ROWB 144                  // bytes per 64-element fp16 row (128 + 16 pad)
#define PARTB (128 * ROWB)        // 18432
#define STAGEB (2 * PARTB)        // 36864: [A, B]
#define GEMM_SMEM (2 * STAGEB)    // 73728

__device__ __forceinline__ void load_chunk(uint32_t st, int bm, int bn, int k0, int tid) {
#pragma unroll
    for (int part = 0; part < 2; part++) {
        const __half* src = part ? g_ph : g_xh;
        const int rbase = part ? bn : bm;
        uint32_t dst = st + part * PARTB;
#pragma unroll
        for (int i = 0; i < 4; i++) {
            int g = tid + i * 256;
            int row = g >> 3, c = g & 7;
            cp16u(dst + row * ROWB + c * 16,
                  src + (size_t)(rbase + row) * DD + k0 + c * 8);
        }
    }
}

__global__ __launch_bounds__(256, 2)
void gemm_mma_kernel() {
    extern __shared__ __align__(16) char smem[];
    __shared__ float dpc[128];
    const uint32_t sb = s2u(smem);
    const int tid = threadIdx.x;
    const int wid = tid >> 5, lane = tid & 31;
    const int g = lane >> 2;
    const int t2 = (lane & 3) * 2;
    const int warpM = wid & 3, warpN = wid >> 2;
    const int bn = blockIdx.x * 128;
    const int bm = blockIdx.y * 128;

    if (tid < 128) dpc[tid] = g_dp[bn + tid];

    const uint32_t aoff = (uint32_t)((warpM * 32 + (lane & 15)) * ROWB + (lane >> 4) * 16);
    const uint32_t boff = (uint32_t)((warpN * 64 + (lane & 15)) * ROWB + (lane >> 4) * 16);

    float d[2][8][4];
#pragma unroll
    for (int mi = 0; mi < 2; mi++)
#pragma unroll
        for (int ni = 0; ni < 8; ni++)
#pragma unroll
            for (int q = 0; q < 4; q++) d[mi][ni][q] = 0.0f;

    load_chunk(sb, bm, bn, 0, tid);
    asm volatile("cp.async.commit_group;");

    for (int s = 0; s < NCHUNK; s++) {
        if (s + 1 < NCHUNK) {
            load_chunk(sb + ((s + 1) & 1) * STAGEB, bm, bn, (s + 1) * BK, tid);
            asm volatile("cp.async.commit_group;");
            asm volatile("cp.async.wait_group 1;");
        } else {
            asm volatile("cp.async.wait_group 0;");
        }
        __syncthreads();

        const uint32_t A = sb + (s & 1) * STAGEB;
        const uint32_t B = A + PARTB;

#pragma unroll
        for (int ks = 0; ks < 4; ks++) {
            unsigned a[2][4], b[4][4];
            ldsm4(a[0], A + aoff + ks * 32);
            ldsm4(a[1], A + aoff + 16 * ROWB + ks * 32);
#pragma unroll
            for (int q = 0; q < 4; q++)
                ldsm4(b[q], B + boff + q * 16 * ROWB + ks * 32);
#pragma unroll
            for (int q = 0; q < 4; q++)
#pragma unroll
                for (int mi = 0; mi < 2; mi++) {
                    mma_f16(d[mi][2 * q],     a[mi], b[q][0], b[q][2]);
                    mma_f16(d[mi][2 * q + 1], a[mi], b[q][1], b[q][3]);
                }
        }
        __syncthreads();
    }

    float tmax = 0.0f;
#pragma unroll
    for (int mi = 0; mi < 2; mi++) {
#pragma unroll
        for (int h = 0; h < 2; h++) {
            int row = bm + warpM * 32 + mi * 16 + h * 8 + g;
            float dxr = g_dx[row];
            float* cp = g_C + (size_t)row * KK + bn + warpN * 64;
#pragma unroll
            for (int ni = 0; ni < 8; ni++) {
                int c0 = ni * 8 + t2;
                float o0 = dxr + dpc[warpN * 64 + c0]     - 2.0f * d[mi][ni][h * 2];
                float o1 = dxr + dpc[warpN * 64 + c0 + 1] - 2.0f * d[mi][ni][h * 2 + 1];
                tmax = fmaxf(tmax, fmaxf(o0, o1));
                *reinterpret_cast<float2*>(cp + c0) = make_float2(o0, o1);
            }
        }
    }
#pragma unroll
    for (int o = 16; o; o >>= 1)
        tmax = fmaxf(tmax, __shfl_xor_sync(0xffffffffu, tmax, o));
    if (!lane) atomicMax(&g_cmax_bits, __float_as_int(tmax));
}

// ---------------- K_eps (fp16, x16 scaled): Kh = 16 * exp(-C / ((max+1e-8)*0.1)) ----------------
__global__ void expk_kernel() {
    float negK = -10.0f / (__int_as_float(g_cmax_bits) + 1e-8f);
    size_t nvec = (size_t)NN * KK / 4;
    size_t stride = (size_t)gridDim.x * blockDim.x;
    for (size_t t = (size_t)blockIdx.x * blockDim.x + threadIdx.x; t < nvec; t += stride) {
        float4 c = *reinterpret_cast<const float4*>(g_C + t * 4);
        __half2 h0 = __floats2half2_rn(__expf(c.x * negK) * HSCALE,
                                       __expf(c.y * negK) * HSCALE);
        __half2 h1 = __floats2half2_rn(__expf(c.z * negK) * HSCALE,
                                       __expf(c.w * negK) * HSCALE);
        uint2 pk;
        pk.x = *reinterpret_cast<unsigned*>(&h0);
        pk.y = *reinterpret_cast<unsigned*>(&h1);
        *reinterpret_cast<uint2*>(g_Kh + t * 4) = pk;
    }
}

// ---------------- fused iteration: v(s[it]) inline, u-step, colacc; L1 prefetch of next pair ----------------
#define RPW 8
#define ROWS_PER_BLOCK (8 * RPW)   // 64 -> 256 blocks
__global__ __launch_bounds__(256, 2)
void fused_uv_kernel(int it) {
    const int tid = threadIdx.x;
    const int lane = tid & 31;
    const int wid  = tid >> 5;
    const int rowbase = blockIdx.x * ROWS_PER_BLOCK + wid * RPW;
    const float* __restrict__ sprev = g_s[it];
    float* __restrict__ snext = g_s[it + 1];

    // v packed as f32x2 pairs matching half2 load layout
    unsigned long long vrp[16];
#pragma unroll
    for (int q = 0; q < 4; q++) {
        int e = (lane + 32 * q) * 8;
        float4 a = *reinterpret_cast<const float4*>(sprev + e);
        float4 b = *reinterpret_cast<const float4*>(sprev + e + 4);
        vrp[4 * q + 0] = pack2(v_of_s(a.x), v_of_s(a.y));
        vrp[4 * q + 1] = pack2(v_of_s(a.z), v_of_s(a.w));
        vrp[4 * q + 2] = pack2(v_of_s(b.x), v_of_s(b.y));
        vrp[4 * q + 3] = pack2(v_of_s(b.z), v_of_s(b.w));
    }
    __half2 colh[16];
#pragma unroll
    for (int j = 0; j < 16; j++) colh[j] = __half2half2(__float2half(0.0f));

#pragma unroll
    for (int pr = 0; pr < RPW / 2; pr++) {
        const int r0 = rowbase + 2 * pr;
        const __half* p0 = g_Kh + (size_t)r0 * KK;
        const __half* p1 = p0 + KK;
        uint4 raw0[4], raw1[4];
#pragma unroll
        for (int q = 0; q < 4; q++) {
            int e = (lane + 32 * q) * 8;
            raw0[q] = *reinterpret_cast<const uint4*>(p0 + e);
            raw1[q] = *reinterpret_cast<const uint4*>(p1 + e);
        }
        // L1-prefetch next pair's segments (no registers consumed)
        if (pr + 1 < RPW / 2) {
            const __half* n0 = p0 + 2 * KK;
            const __half* n1 = p1 + 2 * KK;
#pragma unroll
            for (int q = 0; q < 4; q++) {
                int e = (lane + 32 * q) * 8;
                prefetchL1(n0 + e);
                prefetchL1(n1 + e);
            }
        }
        unsigned long long a0 = 0, b0 = 0, a1 = 0, b1 = 0;
#pragma unroll
        for (int q = 0; q < 4; q++) {
            fma2(a0, h2tof2(raw0[q].x), vrp[4 * q + 0]);
            fma2(b0, h2tof2(raw0[q].y), vrp[4 * q + 1]);
            fma2(a0, h2tof2(raw0[q].z), vrp[4 * q + 2]);
            fma2(b0, h2tof2(raw0[q].w), vrp[4 * q + 3]);
            fma2(a1, h2tof2(raw1[q].x), vrp[4 * q + 0]);
            fma2(b1, h2tof2(raw1[q].y), vrp[4 * q + 1]);
            fma2(a1, h2tof2(raw1[q].z), vrp[4 * q + 2]);
            fma2(b1, h2tof2(raw1[q].w), vrp[4 * q + 3]);
        }
        float2 f0a = unpack2(a0), f0b = unpack2(b0);
        float2 f1a = unpack2(a1), f1b = unpack2(b1);
        float dot0 = (f0a.x + f0a.y) + (f0b.x + f0b.y);
        float dot1 = (f1a.x + f1a.y) + (f1b.x + f1b.y);
#pragma unroll
        for (int o = 16; o; o >>= 1) {
            dot0 += __shfl_xor_sync(0xffffffffu, dot0, o);
            dot1 += __shfl_xor_sync(0xffffffffu, dot1, o);
        }
        float u0 = __fdividef(MU_F, dot0 * INV_HSCALE + 1e-8f);
        float u1 = __fdividef(MU_F, dot1 * INV_HSCALE + 1e-8f);
        if (!lane) {
            g_u[r0] = u0;
            g_u[r0 + 1] = u1;
        }
        __half2 u0h = __float2half2_rn(u0 * USCALE);
        __half2 u1h = __float2half2_rn(u1 * USCALE);
#pragma unroll
        for (int q = 0; q < 4; q++) {
            colh[4*q+0] = __hfma2(u32h2(raw0[q].x), u0h, colh[4*q+0]);
            colh[4*q+1] = __hfma2(u32h2(raw0[q].y), u0h, colh[4*q+1]);
            colh[4*q+2] = __hfma2(u32h2(raw0[q].z), u0h, colh[4*q+2]);
            colh[4*q+3] = __hfma2(u32h2(raw0[q].w), u0h, colh[4*q+3]);
            colh[4*q+0] = __hfma2(u32h2(raw1[q].x), u1h, colh[4*q+0]);
            colh[4*q+1] = __hfma2(u32h2(raw1[q].y), u1h, colh[4*q+1]);
            colh[4*q+2] = __hfma2(u32h2(raw1[q].z), u1h, colh[4*q+2]);
            colh[4*q+3] = __hfma2(u32h2(raw1[q].w), u1h, colh[4*q+3]);
        }
    }

    // block-level reduction of column partials, one atomic per col per block
    __shared__ float sm[8][KK];
#pragma unroll
    for (int q = 0; q < 4; q++) {
        int e = (lane + 32 * q) * 8;
        float2 c0 = __half22float2(colh[4*q+0]);
        float2 c1 = __half22float2(colh[4*q+1]);
        float2 c2 = __half22float2(colh[4*q+2]);
        float2 c3 = __half22float2(colh[4*q+3]);
        *reinterpret_cast<float4*>(&sm[wid][e])     = make_float4(c0.x, c0.y, c1.x, c1.y);
        *reinterpret_cast<float4*>(&sm[wid][e + 4]) = make_float4(c2.x, c2.y, c3.x, c3.y);
    }
    __syncthreads();
#pragma unroll
    for (int c = 0; c < 4; c++) {
        int col = tid + c * 256;
        float s = sm[0][col];
#pragma unroll
        for (int w = 1; w < 8; w++) s += sm[w][col];
        atomicAdd(&snext[col], s);
    }
}

// ---------------- final: read Kh directly. T = u*(Kh/16)*v, Cn = 0.1*(ln16 - ln Kh) ----------------
__global__ __launch_bounds__(256)
void final_kernel(float* __restrict__ out) {
    const float* __restrict__ slast = g_s[ITERS];
    size_t nvec = (size_t)NN * KK / 8;       // 8 halves per thread step
    size_t stride = (size_t)gridDim.x * blockDim.x;
    float lsum = 0.f;
    for (size_t t = (size_t)blockIdx.x * blockDim.x + threadIdx.x; t < nvec; t += stride) {
        size_t base = t * 8;
        int i = (int)(base >> 10);
        int j = (int)(base & 1023);
        uint4 raw = *reinterpret_cast<const uint4*>(g_Kh + base);
        float4 sa = *reinterpret_cast<const float4*>(slast + j);
        float4 sb = *reinterpret_cast<const float4*>(slast + j + 4);
        float ui16 = g_u[i] * INV_HSCALE;    // u / 16 (fold Kh's x16 scale)
        float vj[8] = {v_of_s(sa.x), v_of_s(sa.y), v_of_s(sa.z), v_of_s(sa.w),
                       v_of_s(sb.x), v_of_s(sb.y), v_of_s(sb.z), v_of_s(sb.w)};
        float kh[8];
        float2 f;
        f = __half22float2(u32h2(raw.x)); kh[0] = f.x; kh[1] = f.y;
        f = __half22float2(u32h2(raw.y)); kh[2] = f.x; kh[3] = f.y;
        f = __half22float2(u32h2(raw.z)); kh[4] = f.x; kh[5] = f.y;
        f = __half22float2(u32h2(raw.w)); kh[6] = f.x; kh[7] = f.y;
        float o[8];
#pragma unroll
        for (int q = 0; q < 8; q++) {
            float T = ui16 * kh[q] * vj[q];
            float Cn = 0.1f * (LN16 - __logf(kh[q]));
            o[q] = T;
            lsum = fmaf(T, Cn, lsum);
        }
        *reinterpret_cast<float4*>(out + base)     = make_float4(o[0], o[1], o[2], o[3]);
        *reinterpret_cast<float4*>(out + base + 4) = make_float4(o[4], o[5], o[6], o[7]);
    }
#pragma unroll
    for (int o = 16; o; o >>= 1) lsum += __shfl_xor_sync(0xffffffffu, lsum, o);
    __shared__ float ws[8];
    int lane = threadIdx.x & 31, wid = threadIdx.x >> 5;
    if (!lane) ws[wid] = lsum;
    __syncthreads();
    if (threadIdx.x == 0) {
        float s = 0.f;
#pragma unroll
        for (int i = 0; i < 8; i++) s += ws[i];
        atomicAdd(out + (size_t)NN * KK, s);
    }
}

// ---------------- launch ----------------
extern "C" void kernel_launch(void* const* d_in, const int* in_sizes, int n_in,
                              void* d_out, int out_size) {
    const float* x = (const float*)d_in[0];   // [16384, 512]
    const float* p = (const float*)d_in[1];   // [1024, 512]
    float* out = (float*)d_out;               // T_star [16384,1024] then loss scalar

    cudaFuncSetAttribute(gemm_mma_kernel,
                         cudaFuncAttributeMaxDynamicSharedMemorySize, GEMM_SMEM);

    init_kernel<<<(((ITERS + 1) * KK) + 255) / 256, 256>>>(out);
    split_kernel<<<NN, 128>>>(x, 0);
    split_kernel<<<KK, 128>>>(p, 1);
    gemm_mma_kernel<<<dim3(KK / 128, NN / 128), 256, GEMM_SMEM>>>();
    expk_kernel<<<4096, 256>>>();
    for (int it = 0; it < ITERS; it++)
        fused_uv_kernel<<<NN / ROWS_PER_BLOCK, 256>>>(it);
    final_kernel<<<2048, 256>>>(out);
}